// round 15
// baseline (speedup 1.0000x reference)
#include <cuda_runtime.h>
#include <cuda_bf16.h>
#include <cstdint>

// ---------------------------------------------------------------------------
// BipartiteGATConv — round 15: revert to round-8 all-FFMA2 config (best
// verified, 150.3us) + pack-free FFMA2 inner loop:
//   * A consumed as natural row-pairs (u64 straight from As[k][m])
//   * B stored duplicated in SMEM ((b,b) pairs, padded groups, conflict-free)
//   -> k-step: 6 LDS + 32 FFMA2 + 3 (was 4 LDS + 8 packs + 32 FFMA2 + 4)
// CSR build / aggr / stream fork-join identical to verified round 8.
// ---------------------------------------------------------------------------

#define MAX_N   50000
#define MAX_E   800000
#define FDIM    128
#define HEADS   4
#define SCAN_TILE 1024
#define MAX_SB  ((MAX_N + SCAN_TILE - 1) / SCAN_TILE)

__device__ __align__(16) float g_feat[MAX_N * FDIM];
__device__ __align__(16) float g_asrc[MAX_N * HEADS];
__device__ __align__(16) float g_adst[MAX_N * HEADS];
__device__ __align__(16) float g_fold_v[FDIM * HEADS];
__device__ __align__(16) int   g_deg[MAX_N];
__device__ int   g_row[MAX_N + 1];
__device__ int   g_cursor[MAX_N];
__device__ int   g_bsum[MAX_SB];
__device__ int   g_boff[MAX_SB];
__device__ int   g_csr_s[MAX_E];

typedef unsigned long long u64;

__device__ __forceinline__ float leaky02(float z) {
    return z > 0.f ? z : 0.2f * z;
}

#define FMA_F32X2(d, a, b, c) \
    asm("fma.rn.f32x2 %0, %1, %2, %3;" : "=l"(d) : "l"(a), "l"(b), "l"(c))
#define PACK_DUP_F32X2(d, s) \
    asm("mov.b64 %0, {%1, %1};" : "=l"(d) : "r"(__float_as_uint(s)))
#define UNPACK_F32X2(lo, hi, in) \
    asm("mov.b64 {%0, %1}, %2;" : "=r"(lo), "=r"(hi) : "l"(in))

// ---------------- fold
__global__ void fold_kernel(const float* __restrict__ W_dst,
                            const float* __restrict__ att_dst) {
    int k = threadIdx.x;
    #pragma unroll
    for (int h = 0; h < HEADS; h++) {
        float s = 0.f;
        #pragma unroll 8
        for (int d = 0; d < 32; d++)
            s += W_dst[k * FDIM + h * 32 + d] * att_dst[h * 32 + d];
        g_fold_v[k * HEADS + h] = s;
    }
}

// ---------------- CSR build (unchanged, verified) ----------------
__global__ void zero_deg_kernel(int n) {
    int i = blockIdx.x * blockDim.x + threadIdx.x;
    if (i < n) g_deg[i] = 0;
}

__global__ void hist_kernel(const int* __restrict__ ed, int E) {
    int e = blockIdx.x * blockDim.x + threadIdx.x;
    if (e < E) atomicAdd(&g_deg[ed[e]], 1);
}

__global__ __launch_bounds__(256)
void scan_local_kernel(int n) {
    __shared__ int warp_tot[8];
    int t = threadIdx.x;
    int lane = t & 31, w = t >> 5;
    int base = blockIdx.x * SCAN_TILE + t * 4;

    int4 v = make_int4(0, 0, 0, 0);
    if (base + 3 < n) {
        v = *(const int4*)(g_deg + base);
    } else if (base < n) {
        v.x = g_deg[base];
        if (base + 1 < n) v.y = g_deg[base + 1];
        if (base + 2 < n) v.z = g_deg[base + 2];
    }
    int tot = v.x + v.y + v.z + v.w;

    int inc = tot;
    #pragma unroll
    for (int off = 1; off < 32; off <<= 1) {
        int x = __shfl_up_sync(0xffffffffu, inc, off);
        if (lane >= off) inc += x;
    }
    if (lane == 31) warp_tot[w] = inc;
    __syncthreads();
    if (t < 8) {
        int x = warp_tot[t];
        #pragma unroll
        for (int off = 1; off < 8; off <<= 1) {
            int y = __shfl_up_sync(0xffu, x, off);
            if (t >= off) x += y;
        }
        warp_tot[t] = x;
    }
    __syncthreads();

    int excl = (w > 0 ? warp_tot[w - 1] : 0) + (inc - tot);
    if (base < n) {
        g_row[base] = excl;
        if (base + 1 < n) g_row[base + 1] = excl + v.x;
        if (base + 2 < n) g_row[base + 2] = excl + v.x + v.y;
        if (base + 3 < n) g_row[base + 3] = excl + v.x + v.y + v.z;
    }
    if (t == 0) g_bsum[blockIdx.x] = warp_tot[7];
}

__global__ __launch_bounds__(256)
void scan_bsum_kernel(int nb, int n) {
    __shared__ int s[256];
    int t = threadIdx.x;
    s[t] = (t < nb) ? g_bsum[t] : 0;
    __syncthreads();
    #pragma unroll
    for (int off = 1; off < 256; off <<= 1) {
        int v = (t >= off) ? s[t - off] : 0;
        __syncthreads();
        s[t] += v;
        __syncthreads();
    }
    if (t < nb) g_boff[t] = (t > 0) ? s[t - 1] : 0;
    if (t == 0) g_row[n] = s[255];
}

__global__ __launch_bounds__(256)
void scan_apply_kernel(int n) {
    int t = threadIdx.x;
    int base = blockIdx.x * SCAN_TILE + t * 4;
    int off = g_boff[blockIdx.x];
    #pragma unroll
    for (int j = 0; j < 4; j++) {
        int i = base + j;
        if (i < n) {
            int r = g_row[i] + off;
            g_row[i] = r;
            g_cursor[i] = r;
        }
    }
}

__global__ void scatter_kernel(const int* __restrict__ es,
                               const int* __restrict__ ed, int E) {
    int e = blockIdx.x * blockDim.x + threadIdx.x;
    if (e >= E) return;
    int pos = atomicAdd(&g_cursor[ed[e]], 1);
    g_csr_s[pos] = es[e];
}

// ---------------- aggregate (unchanged, verified)
__global__ __launch_bounds__(256)
void aggr_kernel(float* __restrict__ out, int n_dst) {
    int d = (blockIdx.x * blockDim.x + threadIdx.x) >> 5;
    int lane = threadIdx.x & 31;
    if (d >= n_dst) return;
    int h = lane >> 3;

    int i   = g_row[d];
    int end = g_row[d + 1];
    float adv = g_adst[d * HEADS + h];

    float4 acc = make_float4(0.f, 0.f, 0.f, 0.f);
    float wsum = 0.f;
    const float4* feat4 = (const float4*)g_feat;

    int   s_cur = (i < end) ? g_csr_s[i] : 0;
    float a_cur = (i < end) ? g_asrc[s_cur * HEADS + h] : 0.f;
    for (; i < end; ) {
        int inext = i + 1;
        int   s_nxt = 0;
        float a_nxt = 0.f;
        if (inext < end) {
            s_nxt = g_csr_s[inext];
            a_nxt = g_asrc[s_nxt * HEADS + h];
        }
        float w = __expf(leaky02(a_cur + adv));
        float4 f = feat4[s_cur * 32 + lane];
        acc.x += w * f.x; acc.y += w * f.y;
        acc.z += w * f.z; acc.w += w * f.w;
        wsum += w;
        s_cur = s_nxt; a_cur = a_nxt;
        i = inext;
    }

    float rs = 1.f / (wsum + 1e-16f);
    float4* out4 = (float4*)out;
    float4 o = out4[d * 32 + lane];
    o.x += acc.x * rs; o.y += acc.y * rs;
    o.z += acc.z * rs; o.w += acc.w * rs;
    out4[d * 32 + lane] = o;
}

// ============ FFMA2 GEMM v2: pack-free inner loop =========================
// As[k][m] (m contiguous -> natural row-pair u64s).
// Bd[k][.]: duplicated (b,b) pairs; per-tn group of 16 floats + 4 pad (80B
// stride, conflict-free LDS.128). BDG = group stride in floats.
#define BM 128
#define BN 128
#define BK 16
#define BDG 20
#define BDROW (16 * BDG)   // 320 floats per k-row

template <int MODE>
__global__ __launch_bounds__(256, 2)
void gemm128_kernel(const float* __restrict__ A,
                    const float* __restrict__ B,
                    const float* __restrict__ aux,   // att_src (M0) / bias (M1)
                    float* __restrict__ C,
                    float* __restrict__ alpha_out,
                    int nrows) {
    __shared__ __align__(16) float As[2][BK][BM];
    __shared__ __align__(16) float Bd[2][BK][BDROW];
    __shared__ float xtra[MODE == 0 ? FDIM : FDIM * HEADS];

    int tid = threadIdx.x;
    int tn_idx = tid & 15;
    int tm_idx = tid >> 4;
    int tm0 = tm_idx * 8;
    int tn0 = tn_idx * 8;
    int m0 = blockIdx.x * BM;

    if (MODE == 0) {
        if (tid < FDIM) xtra[tid] = aux[tid];
    } else {
        xtra[tid] = g_fold_v[tid];
        xtra[tid + 256] = g_fold_v[tid + 256];
    }

    // acc2[i2][j]: rows (tm0+2*i2, tm0+2*i2+1) x col tn0+j
    u64 acc2[4][8];
    #pragma unroll
    for (int i = 0; i < 4; i++)
        #pragma unroll
        for (int j = 0; j < 8; j++) acc2[i][j] = 0ull;

    int af_row[2], af_k4[2];
    int bf_k[2], bf_n4[2];
    #pragma unroll
    for (int i = 0; i < 2; i++) {
        int f = tid + i * 256;
        af_row[i] = f >> 2;
        af_k4[i]  = (f & 3) * 4;
        bf_k[i]   = f >> 5;
        bf_n4[i]  = (f & 31) * 4;
    }

    float4 a_reg[2], b_reg[2];
    const float4 zero4 = make_float4(0.f, 0.f, 0.f, 0.f);

    // duplicated-B store helper index: col n -> float offset
    #define BD_IDX(n) (((n) >> 3) * BDG + ((n) & 7) * 2)

    #pragma unroll
    for (int i = 0; i < 2; i++) {
        int grow = m0 + af_row[i];
        a_reg[i] = (grow < nrows)
            ? *(const float4*)(A + (size_t)grow * FDIM + af_k4[i]) : zero4;
        b_reg[i] = *(const float4*)(B + (size_t)bf_k[i] * FDIM + bf_n4[i]);
    }
    #pragma unroll
    for (int i = 0; i < 2; i++) {
        As[0][af_k4[i] + 0][af_row[i]] = a_reg[i].x;
        As[0][af_k4[i] + 1][af_row[i]] = a_reg[i].y;
        As[0][af_k4[i] + 2][af_row[i]] = a_reg[i].z;
        As[0][af_k4[i] + 3][af_row[i]] = a_reg[i].w;
        float* bp = &Bd[0][bf_k[i]][BD_IDX(bf_n4[i])];
        *(float4*)bp       = make_float4(b_reg[i].x, b_reg[i].x,
                                         b_reg[i].y, b_reg[i].y);
        *(float4*)(bp + 4) = make_float4(b_reg[i].z, b_reg[i].z,
                                         b_reg[i].w, b_reg[i].w);
    }
    __syncthreads();

    int h  = tn_idx >> 2;
    int qq = (tn_idx & 3) * 2;
    u64 av2 = 0ull;

    int buf = 0;
    const int NT = FDIM / BK;
    for (int t = 0; t < NT; t++) {
        if (t + 1 < NT) {
            int kt = (t + 1) * BK;
            #pragma unroll
            for (int i = 0; i < 2; i++) {
                int grow = m0 + af_row[i];
                a_reg[i] = (grow < nrows)
                    ? *(const float4*)(A + (size_t)grow * FDIM + kt + af_k4[i]) : zero4;
                b_reg[i] = *(const float4*)(B + (size_t)(kt + bf_k[i]) * FDIM + bf_n4[i]);
            }
        }

        #pragma unroll
        for (int k = 0; k < BK; k++) {
            // a row-pairs: rows tm0..tm0+7 as 4 u64s
            ulonglong2 aq0 = *(const ulonglong2*)&As[buf][k][tm0];
            ulonglong2 aq1 = *(const ulonglong2*)&As[buf][k][tm0 + 4];
            u64 ap[4] = {aq0.x, aq0.y, aq1.x, aq1.y};
            const float* bbase = &Bd[buf][k][tn_idx * BDG];
            #pragma unroll
            for (int jh = 0; jh < 2; jh++) {
                ulonglong2 bq0 = *(const ulonglong2*)(bbase + jh * 8);
                ulonglong2 bq1 = *(const ulonglong2*)(bbase + jh * 8 + 4);
                u64 bd[4] = {bq0.x, bq0.y, bq1.x, bq1.y};
                #pragma unroll
                for (int i2 = 0; i2 < 4; i2++)
                    #pragma unroll
                    for (int j = 0; j < 4; j++)
                        FMA_F32X2(acc2[i2][jh * 4 + j], ap[i2], bd[j],
                                  acc2[i2][jh * 4 + j]);
            }
            if (MODE == 1) {
                float vv = xtra[(t * BK + k) * HEADS + h];
                u64 vvd;
                PACK_DUP_F32X2(vvd, vv);
                FMA_F32X2(av2, ap[qq >> 1], vvd, av2);
            }
        }

        if (t + 1 < NT) {
            int nb = buf ^ 1;
            #pragma unroll
            for (int i = 0; i < 2; i++) {
                As[nb][af_k4[i] + 0][af_row[i]] = a_reg[i].x;
                As[nb][af_k4[i] + 1][af_row[i]] = a_reg[i].y;
                As[nb][af_k4[i] + 2][af_row[i]] = a_reg[i].z;
                As[nb][af_k4[i] + 3][af_row[i]] = a_reg[i].w;
                float* bp = &Bd[nb][bf_k[i]][BD_IDX(bf_n4[i])];
                *(float4*)bp       = make_float4(b_reg[i].x, b_reg[i].x,
                                                 b_reg[i].y, b_reg[i].y);
                *(float4*)(bp + 4) = make_float4(b_reg[i].z, b_reg[i].z,
                                                 b_reg[i].w, b_reg[i].w);
            }
            __syncthreads();
            buf = nb;
        }
    }

    // unpack: acc[row][col]
    float acc[8][8];
    #pragma unroll
    for (int i2 = 0; i2 < 4; i2++)
        #pragma unroll
        for (int j = 0; j < 8; j++) {
            unsigned lo, hi;
            UNPACK_F32X2(lo, hi, acc2[i2][j]);
            acc[2 * i2][j]     = __uint_as_float(lo);
            acc[2 * i2 + 1][j] = __uint_as_float(hi);
        }

    float4 bb0 = zero4, bb1 = zero4;
    if (MODE == 1) {
        bb0 = *(const float4*)(aux + tn0);
        bb1 = *(const float4*)(aux + tn0 + 4);
    }
    #pragma unroll
    for (int i = 0; i < 8; i++) {
        int row = m0 + tm0 + i;
        if (row < nrows) {
            float4 o0 = make_float4(acc[i][0] + bb0.x, acc[i][1] + bb0.y,
                                    acc[i][2] + bb0.z, acc[i][3] + bb0.w);
            float4 o1 = make_float4(acc[i][4] + bb1.x, acc[i][5] + bb1.y,
                                    acc[i][6] + bb1.z, acc[i][7] + bb1.w);
            *(float4*)(C + (size_t)row * FDIM + tn0)     = o0;
            *(float4*)(C + (size_t)row * FDIM + tn0 + 4) = o1;
        }
    }

    if (MODE == 0) {
        float a_att[8];
        #pragma unroll
        for (int j = 0; j < 8; j++) a_att[j] = xtra[tn0 + j];
        #pragma unroll
        for (int i = 0; i < 8; i++) {
            float p = 0.f;
            #pragma unroll
            for (int j = 0; j < 8; j++) p += acc[i][j] * a_att[j];
            p += __shfl_xor_sync(0xffffffffu, p, 1);
            p += __shfl_xor_sync(0xffffffffu, p, 2);
            if ((tn_idx & 3) == 0) {
                int row = m0 + tm0 + i;
                if (row < nrows) alpha_out[row * HEADS + h] = p;
            }
        }
    } else {
        unsigned lo, hi;
        UNPACK_F32X2(lo, hi, av2);
        int r0 = m0 + tm0 + qq;
        if (r0 < nrows)     alpha_out[r0 * HEADS + h]       = __uint_as_float(lo);
        if (r0 + 1 < nrows) alpha_out[(r0 + 1) * HEADS + h] = __uint_as_float(hi);
    }
    #undef BD_IDX
}

// ---------------------------------------------------------------------------
extern "C" void kernel_launch(void* const* d_in, const int* in_sizes, int n_in,
                              void* d_out, int out_size) {
    const float* x_src    = (const float*)d_in[0];
    const float* x_dst    = (const float*)d_in[1];
    const int*   edge_src = (const int*)d_in[2];
    const int*   edge_dst = (const int*)d_in[3];
    int off = (n_in >= 11) ? 5 : 4;
    const float* W_src   = (const float*)d_in[off + 0];
    const float* W_dst   = (const float*)d_in[off + 1];
    const float* att_src = (const float*)d_in[off + 2];
    const float* att_dst = (const float*)d_in[off + 3];
    const float* W_self  = (const float*)d_in[off + 4];
    const float* b_self  = (const float*)d_in[off + 5];
    float* out = (float*)d_out;

    int n_src = in_sizes[0] / FDIM;
    int n_dst = in_sizes[1] / FDIM;
    int E     = in_sizes[2];

    static float* p_feat = nullptr;
    static float* p_asrc = nullptr;
    static float* p_adst = nullptr;
    static cudaStream_t s1 = nullptr, s2 = nullptr;
    static cudaEvent_t ev_fork = nullptr, ev_g1 = nullptr, ev_csr = nullptr;
    if (!p_feat) {
        cudaGetSymbolAddress((void**)&p_feat, g_feat);
        cudaGetSymbolAddress((void**)&p_asrc, g_asrc);
        cudaGetSymbolAddress((void**)&p_adst, g_adst);
        cudaStreamCreateWithFlags(&s1, cudaStreamNonBlocking);
        cudaStreamCreateWithFlags(&s2, cudaStreamNonBlocking);
        cudaEventCreateWithFlags(&ev_fork, cudaEventDisableTiming);
        cudaEventCreateWithFlags(&ev_g1,   cudaEventDisableTiming);
        cudaEventCreateWithFlags(&ev_csr,  cudaEventDisableTiming);
    }

    int nb = (n_dst + SCAN_TILE - 1) / SCAN_TILE;

    // main: fold (needed by gemm<1>)
    fold_kernel<<<1, 128>>>(W_dst, att_dst);

    cudaEventRecord(ev_fork, 0);
    cudaStreamWaitEvent(s1, ev_fork, 0);
    cudaStreamWaitEvent(s2, ev_fork, 0);

    // s2: CSR build
    zero_deg_kernel<<<(n_dst + 255) / 256, 256, 0, s2>>>(n_dst);
    hist_kernel<<<(E + 255) / 256, 256, 0, s2>>>(edge_dst, E);
    scan_local_kernel<<<nb, 256, 0, s2>>>(n_dst);
    scan_bsum_kernel<<<1, 256, 0, s2>>>(nb, n_dst);
    scan_apply_kernel<<<nb, 256, 0, s2>>>(n_dst);
    scatter_kernel<<<(E + 255) / 256, 256, 0, s2>>>(edge_src, edge_dst, E);
    cudaEventRecord(ev_csr, s2);

    // s1: dst GEMM (out self-term + alpha_dst)
    gemm128_kernel<1><<<(n_dst + BM - 1) / BM, 256, 0, s1>>>(
        x_dst, W_self, b_self, out, p_adst, n_dst);
    cudaEventRecord(ev_g1, s1);

    // main: src GEMM (feat + alpha_src)
    gemm128_kernel<0><<<(n_src + BM - 1) / BM, 256>>>(
        x_src, W_src, att_src, p_feat, p_asrc, n_src);

    // join
    cudaStreamWaitEvent(0, ev_g1, 0);
    cudaStreamWaitEvent(0, ev_csr, 0);
    long long total_threads = (long long)n_dst * 32;
    int blocks = (int)((total_threads + 255) / 256);
    aggr_kernel<<<blocks, 256>>>(out, n_dst);
}

// round 16
// speedup vs baseline: 1.0347x; 1.0347x over previous
#include <cuda_runtime.h>
#include <cuda_bf16.h>
#include <cstdint>

// ---------------------------------------------------------------------------
// BipartiteGATConv — round 16: round-8 kernels (best verified), rescheduled so
// the mem-bound aggregate overlaps the fma-bound dst GEMM:
//   gemm0(feat+asrc) -> { aggr->g_agg  ||  gemm1(out=x@W+b) } -> out += g_agg
// alpha_dst decoupled from gemm1 via the round-3 GEMV (hides under gemm0).
// ---------------------------------------------------------------------------

#define MAX_N   50000
#define MAX_E   800000
#define FDIM    128
#define HEADS   4
#define SCAN_TILE 1024
#define MAX_SB  ((MAX_N + SCAN_TILE - 1) / SCAN_TILE)

__device__ __align__(16) float g_feat[MAX_N * FDIM];
__device__ __align__(16) float g_agg[MAX_N * FDIM];
__device__ __align__(16) float g_asrc[MAX_N * HEADS];
__device__ __align__(16) float g_adst[MAX_N * HEADS];
__device__ __align__(16) float g_fold_v[FDIM * HEADS];
__device__ __align__(16) int   g_deg[MAX_N];
__device__ int   g_row[MAX_N + 1];
__device__ int   g_cursor[MAX_N];
__device__ int   g_bsum[MAX_SB];
__device__ int   g_boff[MAX_SB];
__device__ int   g_csr_s[MAX_E];

typedef unsigned long long u64;

__device__ __forceinline__ float leaky02(float z) {
    return z > 0.f ? z : 0.2f * z;
}

#define FMA_F32X2(d, a, b, c) \
    asm("fma.rn.f32x2 %0, %1, %2, %3;" : "=l"(d) : "l"(a), "l"(b), "l"(c))
#define PACK_DUP_F32X2(d, s) \
    asm("mov.b64 %0, {%1, %1};" : "=l"(d) : "r"(__float_as_uint(s)))
#define UNPACK_F32X2(lo, hi, in) \
    asm("mov.b64 {%0, %1}, %2;" : "=r"(lo), "=r"(hi) : "l"(in))

// ---------------- fold: v[k,h] = sum_d W_dst[k, h*32+d] * att_dst[h*32+d]
__global__ void fold_kernel(const float* __restrict__ W_dst,
                            const float* __restrict__ att_dst) {
    int k = threadIdx.x;
    #pragma unroll
    for (int h = 0; h < HEADS; h++) {
        float s = 0.f;
        #pragma unroll 8
        for (int d = 0; d < 32; d++)
            s += W_dst[k * FDIM + h * 32 + d] * att_dst[h * 32 + d];
        g_fold_v[k * HEADS + h] = s;
    }
}

// ---------------- alpha GEMV (round-3 verified): out[n,4] = x[n,128]@fold
__global__ __launch_bounds__(256)
void alpha_kernel(const float* __restrict__ x,
                  const float* __restrict__ fold,
                  float* __restrict__ out, int n) {
    __shared__ float usm[FDIM * HEADS];
    int tid = threadIdx.x;
    usm[tid] = fold[tid];
    usm[tid + 256] = fold[tid + 256];
    __syncthreads();

    int warp = tid >> 5, lane = tid & 31;
    int row = blockIdx.x * 32 + warp * 4 + (lane >> 3);
    if (row >= n) return;
    int kbase = (lane & 7) * 16;

    const float4* xr = (const float4*)(x + (size_t)row * FDIM + kbase);
    const float4* u4base = ((const float4*)usm) + kbase;
    float4 p = make_float4(0.f, 0.f, 0.f, 0.f);
    #pragma unroll
    for (int j = 0; j < 4; j++) {
        float4 xv = xr[j];
        float4 u0 = u4base[j * 4 + 0];
        float4 u1 = u4base[j * 4 + 1];
        float4 u2 = u4base[j * 4 + 2];
        float4 u3 = u4base[j * 4 + 3];
        p.x += xv.x * u0.x + xv.y * u1.x + xv.z * u2.x + xv.w * u3.x;
        p.y += xv.x * u0.y + xv.y * u1.y + xv.z * u2.y + xv.w * u3.y;
        p.z += xv.x * u0.z + xv.y * u1.z + xv.z * u2.z + xv.w * u3.z;
        p.w += xv.x * u0.w + xv.y * u1.w + xv.z * u2.w + xv.w * u3.w;
    }
    #pragma unroll
    for (int m = 4; m >= 1; m >>= 1) {
        p.x += __shfl_xor_sync(0xffffffffu, p.x, m);
        p.y += __shfl_xor_sync(0xffffffffu, p.y, m);
        p.z += __shfl_xor_sync(0xffffffffu, p.z, m);
        p.w += __shfl_xor_sync(0xffffffffu, p.w, m);
    }
    if ((lane & 7) == 0) ((float4*)out)[row] = p;
}

// ---------------- CSR build (unchanged, verified) ----------------
__global__ void zero_deg_kernel(int n) {
    int i = blockIdx.x * blockDim.x + threadIdx.x;
    if (i < n) g_deg[i] = 0;
}

__global__ void hist_kernel(const int* __restrict__ ed, int E) {
    int e = blockIdx.x * blockDim.x + threadIdx.x;
    if (e < E) atomicAdd(&g_deg[ed[e]], 1);
}

__global__ __launch_bounds__(256)
void scan_local_kernel(int n) {
    __shared__ int warp_tot[8];
    int t = threadIdx.x;
    int lane = t & 31, w = t >> 5;
    int base = blockIdx.x * SCAN_TILE + t * 4;

    int4 v = make_int4(0, 0, 0, 0);
    if (base + 3 < n) {
        v = *(const int4*)(g_deg + base);
    } else if (base < n) {
        v.x = g_deg[base];
        if (base + 1 < n) v.y = g_deg[base + 1];
        if (base + 2 < n) v.z = g_deg[base + 2];
    }
    int tot = v.x + v.y + v.z + v.w;

    int inc = tot;
    #pragma unroll
    for (int off = 1; off < 32; off <<= 1) {
        int x = __shfl_up_sync(0xffffffffu, inc, off);
        if (lane >= off) inc += x;
    }
    if (lane == 31) warp_tot[w] = inc;
    __syncthreads();
    if (t < 8) {
        int x = warp_tot[t];
        #pragma unroll
        for (int off = 1; off < 8; off <<= 1) {
            int y = __shfl_up_sync(0xffu, x, off);
            if (t >= off) x += y;
        }
        warp_tot[t] = x;
    }
    __syncthreads();

    int excl = (w > 0 ? warp_tot[w - 1] : 0) + (inc - tot);
    if (base < n) {
        g_row[base] = excl;
        if (base + 1 < n) g_row[base + 1] = excl + v.x;
        if (base + 2 < n) g_row[base + 2] = excl + v.x + v.y;
        if (base + 3 < n) g_row[base + 3] = excl + v.x + v.y + v.z;
    }
    if (t == 0) g_bsum[blockIdx.x] = warp_tot[7];
}

__global__ __launch_bounds__(256)
void scan_bsum_kernel(int nb, int n) {
    __shared__ int s[256];
    int t = threadIdx.x;
    s[t] = (t < nb) ? g_bsum[t] : 0;
    __syncthreads();
    #pragma unroll
    for (int off = 1; off < 256; off <<= 1) {
        int v = (t >= off) ? s[t - off] : 0;
        __syncthreads();
        s[t] += v;
        __syncthreads();
    }
    if (t < nb) g_boff[t] = (t > 0) ? s[t - 1] : 0;
    if (t == 0) g_row[n] = s[255];
}

__global__ __launch_bounds__(256)
void scan_apply_kernel(int n) {
    int t = threadIdx.x;
    int base = blockIdx.x * SCAN_TILE + t * 4;
    int off = g_boff[blockIdx.x];
    #pragma unroll
    for (int j = 0; j < 4; j++) {
        int i = base + j;
        if (i < n) {
            int r = g_row[i] + off;
            g_row[i] = r;
            g_cursor[i] = r;
        }
    }
}

__global__ void scatter_kernel(const int* __restrict__ es,
                               const int* __restrict__ ed, int E) {
    int e = blockIdx.x * blockDim.x + threadIdx.x;
    if (e >= E) return;
    int pos = atomicAdd(&g_cursor[ed[e]], 1);
    g_csr_s[pos] = es[e];
}

// ---------------- aggregate -> scratch (round-8 aggr minus the out RMW)
__global__ __launch_bounds__(256)
void aggr_kernel(int n_dst) {
    int d = (blockIdx.x * blockDim.x + threadIdx.x) >> 5;
    int lane = threadIdx.x & 31;
    if (d >= n_dst) return;
    int h = lane >> 3;

    int i   = g_row[d];
    int end = g_row[d + 1];
    float adv = g_adst[d * HEADS + h];

    float4 acc = make_float4(0.f, 0.f, 0.f, 0.f);
    float wsum = 0.f;
    const float4* feat4 = (const float4*)g_feat;

    int   s_cur = (i < end) ? g_csr_s[i] : 0;
    float a_cur = (i < end) ? g_asrc[s_cur * HEADS + h] : 0.f;
    for (; i < end; ) {
        int inext = i + 1;
        int   s_nxt = 0;
        float a_nxt = 0.f;
        if (inext < end) {
            s_nxt = g_csr_s[inext];
            a_nxt = g_asrc[s_nxt * HEADS + h];
        }
        float w = __expf(leaky02(a_cur + adv));
        float4 f = feat4[s_cur * 32 + lane];
        acc.x += w * f.x; acc.y += w * f.y;
        acc.z += w * f.z; acc.w += w * f.w;
        wsum += w;
        s_cur = s_nxt; a_cur = a_nxt;
        i = inext;
    }

    float rs = 1.f / (wsum + 1e-16f);
    acc.x *= rs; acc.y *= rs; acc.z *= rs; acc.w *= rs;
    ((float4*)g_agg)[d * 32 + lane] = acc;
}

// ---------------- final: out += g_agg
__global__ __launch_bounds__(256)
void add_kernel(float* __restrict__ out, int n4) {
    int i = blockIdx.x * blockDim.x + threadIdx.x;
    if (i >= n4) return;
    float4 o = ((const float4*)out)[i];
    float4 a = ((const float4*)g_agg)[i];
    o.x += a.x; o.y += a.y; o.z += a.z; o.w += a.w;
    ((float4*)out)[i] = o;
}

// ---------------- round-8 FFMA2 GEMM (verified):
// MODE 0: C=feat + alpha_src epilogue.  MODE 1: C = A@B + bias (no alpha).
#define BM 128
#define BN 128
#define BK 16
#define TM 8
#define TN 8

template <int MODE>
__global__ __launch_bounds__(256, 2)
void gemm128_kernel(const float* __restrict__ A,
                    const float* __restrict__ B,
                    const float* __restrict__ aux,   // att_src (M0) / bias (M1)
                    float* __restrict__ C,
                    float* __restrict__ alpha_out,
                    int nrows) {
    __shared__ float As[2][BK][BM];
    __shared__ __align__(16) float Bs[2][BK][BN];
    __shared__ float xtra[FDIM];

    int tid = threadIdx.x;
    int tn_idx = tid & 15;
    int tm_idx = tid >> 4;
    int tm0 = tm_idx * TM;
    int tn0 = tn_idx * TN;
    int m0 = blockIdx.x * BM;

    if (tid < FDIM) xtra[tid] = aux[tid];

    u64 acc2[TM][TN / 2];
    #pragma unroll
    for (int i = 0; i < TM; i++)
        #pragma unroll
        for (int j = 0; j < TN / 2; j++) acc2[i][j] = 0ull;

    int af_row[2], af_k4[2];
    int bf_k[2], bf_n4[2];
    #pragma unroll
    for (int i = 0; i < 2; i++) {
        int f = tid + i * 256;
        af_row[i] = f >> 2;
        af_k4[i]  = (f & 3) * 4;
        bf_k[i]   = f >> 5;
        bf_n4[i]  = (f & 31) * 4;
    }

    float4 a_reg[2], b_reg[2];
    const float4 zero4 = make_float4(0.f, 0.f, 0.f, 0.f);

    #pragma unroll
    for (int i = 0; i < 2; i++) {
        int grow = m0 + af_row[i];
        a_reg[i] = (grow < nrows)
            ? *(const float4*)(A + (size_t)grow * FDIM + af_k4[i]) : zero4;
        b_reg[i] = *(const float4*)(B + (size_t)bf_k[i] * FDIM + bf_n4[i]);
    }
    #pragma unroll
    for (int i = 0; i < 2; i++) {
        As[0][af_k4[i] + 0][af_row[i]] = a_reg[i].x;
        As[0][af_k4[i] + 1][af_row[i]] = a_reg[i].y;
        As[0][af_k4[i] + 2][af_row[i]] = a_reg[i].z;
        As[0][af_k4[i] + 3][af_row[i]] = a_reg[i].w;
        *(float4*)&Bs[0][bf_k[i]][bf_n4[i]] = b_reg[i];
    }
    __syncthreads();

    int buf = 0;
    const int NT = FDIM / BK;
    for (int t = 0; t < NT; t++) {
        if (t + 1 < NT) {
            int kt = (t + 1) * BK;
            #pragma unroll
            for (int i = 0; i < 2; i++) {
                int grow = m0 + af_row[i];
                a_reg[i] = (grow < nrows)
                    ? *(const float4*)(A + (size_t)grow * FDIM + kt + af_k4[i]) : zero4;
                b_reg[i] = *(const float4*)(B + (size_t)(kt + bf_k[i]) * FDIM + bf_n4[i]);
            }
        }

        #pragma unroll
        for (int k = 0; k < BK; k++) {
            float4 a0 = *(const float4*)&As[buf][k][tm0];
            float4 a1 = *(const float4*)&As[buf][k][tm0 + 4];
            ulonglong2 bq0 = *(const ulonglong2*)&Bs[buf][k][tn0];
            ulonglong2 bq1 = *(const ulonglong2*)&Bs[buf][k][tn0 + 4];
            u64 bp[4] = {bq0.x, bq0.y, bq1.x, bq1.y};
            float avv[TM] = {a0.x, a0.y, a0.z, a0.w, a1.x, a1.y, a1.z, a1.w};
            #pragma unroll
            for (int i = 0; i < TM; i++) {
                u64 ad;
                PACK_DUP_F32X2(ad, avv[i]);
                #pragma unroll
                for (int j = 0; j < TN / 2; j++)
                    FMA_F32X2(acc2[i][j], ad, bp[j], acc2[i][j]);
            }
        }

        if (t + 1 < NT) {
            int nb = buf ^ 1;
            #pragma unroll
            for (int i = 0; i < 2; i++) {
                As[nb][af_k4[i] + 0][af_row[i]] = a_reg[i].x;
                As[nb][af_k4[i] + 1][af_row[i]] = a_reg[i].y;
                As[nb][af_k4[i] + 2][af_row[i]] = a_reg[i].z;
                As[nb][af_k4[i] + 3][af_row[i]] = a_reg[i].w;
                *(float4*)&Bs[nb][bf_k[i]][bf_n4[i]] = b_reg[i];
            }
            __syncthreads();
            buf = nb;
        }
    }

    float acc[TM][TN];
    #pragma unroll
    for (int i = 0; i < TM; i++)
        #pragma unroll
        for (int j = 0; j < TN / 2; j++) {
            unsigned lo, hi;
            UNPACK_F32X2(lo, hi, acc2[i][j]);
            acc[i][2 * j]     = __uint_as_float(lo);
            acc[i][2 * j + 1] = __uint_as_float(hi);
        }

    float4 bb0 = zero4, bb1 = zero4;
    if (MODE == 1) {
        bb0 = *(const float4*)(aux + tn0);
        bb1 = *(const float4*)(aux + tn0 + 4);
    }
    #pragma unroll
    for (int i = 0; i < TM; i++) {
        int row = m0 + tm0 + i;
        if (row < nrows) {
            float4 o0 = make_float4(acc[i][0] + bb0.x, acc[i][1] + bb0.y,
                                    acc[i][2] + bb0.z, acc[i][3] + bb0.w);
            float4 o1 = make_float4(acc[i][4] + bb1.x, acc[i][5] + bb1.y,
                                    acc[i][6] + bb1.z, acc[i][7] + bb1.w);
            *(float4*)(C + (size_t)row * FDIM + tn0)     = o0;
            *(float4*)(C + (size_t)row * FDIM + tn0 + 4) = o1;
        }
    }

    if (MODE == 0) {
        int h = tn_idx >> 2;
        float a_att[TN];
        #pragma unroll
        for (int j = 0; j < TN; j++) a_att[j] = xtra[tn0 + j];
        #pragma unroll
        for (int i = 0; i < TM; i++) {
            float p = 0.f;
            #pragma unroll
            for (int j = 0; j < TN; j++) p += acc[i][j] * a_att[j];
            p += __shfl_xor_sync(0xffffffffu, p, 1);
            p += __shfl_xor_sync(0xffffffffu, p, 2);
            if ((tn_idx & 3) == 0) {
                int row = m0 + tm0 + i;
                if (row < nrows) alpha_out[row * HEADS + h] = p;
            }
        }
    }
}

// ---------------------------------------------------------------------------
extern "C" void kernel_launch(void* const* d_in, const int* in_sizes, int n_in,
                              void* d_out, int out_size) {
    const float* x_src    = (const float*)d_in[0];
    const float* x_dst    = (const float*)d_in[1];
    const int*   edge_src = (const int*)d_in[2];
    const int*   edge_dst = (const int*)d_in[3];
    int off = (n_in >= 11) ? 5 : 4;
    const float* W_src   = (const float*)d_in[off + 0];
    const float* W_dst   = (const float*)d_in[off + 1];
    const float* att_src = (const float*)d_in[off + 2];
    const float* att_dst = (const float*)d_in[off + 3];
    const float* W_self  = (const float*)d_in[off + 4];
    const float* b_self  = (const float*)d_in[off + 5];
    float* out = (float*)d_out;

    int n_src = in_sizes[0] / FDIM;
    int n_dst = in_sizes[1] / FDIM;
    int E     = in_sizes[2];

    static float* p_feat = nullptr;
    static float* p_asrc = nullptr;
    static float* p_adst = nullptr;
    static float* p_fold = nullptr;
    static cudaStream_t s1 = nullptr, s2 = nullptr, s3 = nullptr;
    static cudaEvent_t ev_fork = nullptr, ev_g0 = nullptr, ev_g1 = nullptr,
                       ev_csr = nullptr, ev_adst = nullptr;
    if (!p_feat) {
        cudaGetSymbolAddress((void**)&p_feat, g_feat);
        cudaGetSymbolAddress((void**)&p_asrc, g_asrc);
        cudaGetSymbolAddress((void**)&p_adst, g_adst);
        cudaGetSymbolAddress((void**)&p_fold, g_fold_v);
        cudaStreamCreateWithFlags(&s1, cudaStreamNonBlocking);
        cudaStreamCreateWithFlags(&s2, cudaStreamNonBlocking);
        cudaStreamCreateWithFlags(&s3, cudaStreamNonBlocking);
        cudaEventCreateWithFlags(&ev_fork, cudaEventDisableTiming);
        cudaEventCreateWithFlags(&ev_g0,   cudaEventDisableTiming);
        cudaEventCreateWithFlags(&ev_g1,   cudaEventDisableTiming);
        cudaEventCreateWithFlags(&ev_csr,  cudaEventDisableTiming);
        cudaEventCreateWithFlags(&ev_adst, cudaEventDisableTiming);
    }

    int nb = (n_dst + SCAN_TILE - 1) / SCAN_TILE;

    // fork everything off the capture-origin stream
    cudaEventRecord(ev_fork, 0);
    cudaStreamWaitEvent(s1, ev_fork, 0);
    cudaStreamWaitEvent(s2, ev_fork, 0);
    cudaStreamWaitEvent(s3, ev_fork, 0);

    // s1: fold -> alpha_dst GEMV (DRAM-bound, hides under gemm0)
    fold_kernel<<<1, 128, 0, s1>>>(W_dst, att_dst);
    alpha_kernel<<<(n_dst + 31) / 32, 256, 0, s1>>>(x_dst, p_fold, p_adst, n_dst);
    cudaEventRecord(ev_adst, s1);

    // s2: CSR build (hides under gemm0)
    zero_deg_kernel<<<(n_dst + 255) / 256, 256, 0, s2>>>(n_dst);
    hist_kernel<<<(E + 255) / 256, 256, 0, s2>>>(edge_dst, E);
    scan_local_kernel<<<nb, 256, 0, s2>>>(n_dst);
    scan_bsum_kernel<<<1, 256, 0, s2>>>(nb, n_dst);
    scan_apply_kernel<<<nb, 256, 0, s2>>>(n_dst);
    scatter_kernel<<<(E + 255) / 256, 256, 0, s2>>>(edge_src, edge_dst, E);
    cudaEventRecord(ev_csr, s2);

    // main: src GEMM first (everything downstream needs feat/asrc)
    gemm128_kernel<0><<<(n_src + BM - 1) / BM, 256>>>(
        x_src, W_src, att_src, p_feat, p_asrc, n_src);
    cudaEventRecord(ev_g0, 0);

    // s3: dst GEMM (fma-bound) AFTER gemm0, CONCURRENT with aggr (mem-bound)
    cudaStreamWaitEvent(s3, ev_g0, 0);
    gemm128_kernel<1><<<(n_dst + BM - 1) / BM, 256, 0, s3>>>(
        x_dst, W_self, b_self, out, nullptr, n_dst);
    cudaEventRecord(ev_g1, s3);

    // main: aggregate into scratch (needs gemm0 + adst + CSR)
    cudaStreamWaitEvent(0, ev_adst, 0);
    cudaStreamWaitEvent(0, ev_csr, 0);
    long long total_threads = (long long)n_dst * 32;
    int blocks = (int)((total_threads + 255) / 256);
    aggr_kernel<<<blocks, 256>>>(n_dst);

    // main: final add after both aggr (in-stream) and gemm1
    cudaStreamWaitEvent(0, ev_g1, 0);
    int n4 = n_dst * 32;
    add_kernel<<<(n4 + 255) / 256, 256>>>(out, n4);
}

// round 17
// speedup vs baseline: 1.0382x; 1.0034x over previous
#include <cuda_runtime.h>
#include <cuda_bf16.h>
#include <cstdint>

// ---------------------------------------------------------------------------
// BipartiteGATConv — round 17: round-8 structure EXACTLY (best verified,
// 150.3us) with one inner-loop fix: A stored DUPLICATED in smem so the FFMA2
// a-operand (a,a) pairs load directly (broadcast, conflict-free) — removes
// all 8 mov.b64 packs per k-step (47 -> ~39 issues per 32 FFMA2).
// ---------------------------------------------------------------------------

#define MAX_N   50000
#define MAX_E   800000
#define FDIM    128
#define HEADS   4
#define SCAN_TILE 1024
#define MAX_SB  ((MAX_N + SCAN_TILE - 1) / SCAN_TILE)

__device__ __align__(16) float g_feat[MAX_N * FDIM];
__device__ __align__(16) float g_asrc[MAX_N * HEADS];
__device__ __align__(16) float g_adst[MAX_N * HEADS];
__device__ __align__(16) float g_fold_v[FDIM * HEADS];
__device__ __align__(16) int   g_deg[MAX_N];
__device__ int   g_row[MAX_N + 1];
__device__ int   g_cursor[MAX_N];
__device__ int   g_bsum[MAX_SB];
__device__ int   g_boff[MAX_SB];
__device__ int   g_csr_s[MAX_E];

typedef unsigned long long u64;

__device__ __forceinline__ float leaky02(float z) {
    return z > 0.f ? z : 0.2f * z;
}

#define FMA_F32X2(d, a, b, c) \
    asm("fma.rn.f32x2 %0, %1, %2, %3;" : "=l"(d) : "l"(a), "l"(b), "l"(c))
#define PACK_DUP_F32X2(d, s) \
    asm("mov.b64 %0, {%1, %1};" : "=l"(d) : "r"(__float_as_uint(s)))
#define UNPACK_F32X2(lo, hi, in) \
    asm("mov.b64 {%0, %1}, %2;" : "=r"(lo), "=r"(hi) : "l"(in))

// ---------------- fold
__global__ void fold_kernel(const float* __restrict__ W_dst,
                            const float* __restrict__ att_dst) {
    int k = threadIdx.x;
    #pragma unroll
    for (int h = 0; h < HEADS; h++) {
        float s = 0.f;
        #pragma unroll 8
        for (int d = 0; d < 32; d++)
            s += W_dst[k * FDIM + h * 32 + d] * att_dst[h * 32 + d];
        g_fold_v[k * HEADS + h] = s;
    }
}

// ---------------- CSR build (unchanged, verified) ----------------
__global__ void zero_deg_kernel(int n) {
    int i = blockIdx.x * blockDim.x + threadIdx.x;
    if (i < n) g_deg[i] = 0;
}

__global__ void hist_kernel(const int* __restrict__ ed, int E) {
    int e = blockIdx.x * blockDim.x + threadIdx.x;
    if (e < E) atomicAdd(&g_deg[ed[e]], 1);
}

__global__ __launch_bounds__(256)
void scan_local_kernel(int n) {
    __shared__ int warp_tot[8];
    int t = threadIdx.x;
    int lane = t & 31, w = t >> 5;
    int base = blockIdx.x * SCAN_TILE + t * 4;

    int4 v = make_int4(0, 0, 0, 0);
    if (base + 3 < n) {
        v = *(const int4*)(g_deg + base);
    } else if (base < n) {
        v.x = g_deg[base];
        if (base + 1 < n) v.y = g_deg[base + 1];
        if (base + 2 < n) v.z = g_deg[base + 2];
    }
    int tot = v.x + v.y + v.z + v.w;

    int inc = tot;
    #pragma unroll
    for (int off = 1; off < 32; off <<= 1) {
        int x = __shfl_up_sync(0xffffffffu, inc, off);
        if (lane >= off) inc += x;
    }
    if (lane == 31) warp_tot[w] = inc;
    __syncthreads();
    if (t < 8) {
        int x = warp_tot[t];
        #pragma unroll
        for (int off = 1; off < 8; off <<= 1) {
            int y = __shfl_up_sync(0xffu, x, off);
            if (t >= off) x += y;
        }
        warp_tot[t] = x;
    }
    __syncthreads();

    int excl = (w > 0 ? warp_tot[w - 1] : 0) + (inc - tot);
    if (base < n) {
        g_row[base] = excl;
        if (base + 1 < n) g_row[base + 1] = excl + v.x;
        if (base + 2 < n) g_row[base + 2] = excl + v.x + v.y;
        if (base + 3 < n) g_row[base + 3] = excl + v.x + v.y + v.z;
    }
    if (t == 0) g_bsum[blockIdx.x] = warp_tot[7];
}

__global__ __launch_bounds__(256)
void scan_bsum_kernel(int nb, int n) {
    __shared__ int s[256];
    int t = threadIdx.x;
    s[t] = (t < nb) ? g_bsum[t] : 0;
    __syncthreads();
    #pragma unroll
    for (int off = 1; off < 256; off <<= 1) {
        int v = (t >= off) ? s[t - off] : 0;
        __syncthreads();
        s[t] += v;
        __syncthreads();
    }
    if (t < nb) g_boff[t] = (t > 0) ? s[t - 1] : 0;
    if (t == 0) g_row[n] = s[255];
}

__global__ __launch_bounds__(256)
void scan_apply_kernel(int n) {
    int t = threadIdx.x;
    int base = blockIdx.x * SCAN_TILE + t * 4;
    int off = g_boff[blockIdx.x];
    #pragma unroll
    for (int j = 0; j < 4; j++) {
        int i = base + j;
        if (i < n) {
            int r = g_row[i] + off;
            g_row[i] = r;
            g_cursor[i] = r;
        }
    }
}

__global__ void scatter_kernel(const int* __restrict__ es,
                               const int* __restrict__ ed, int E) {
    int e = blockIdx.x * blockDim.x + threadIdx.x;
    if (e >= E) return;
    int pos = atomicAdd(&g_cursor[ed[e]], 1);
    g_csr_s[pos] = es[e];
}

// ---------------- aggregate (unchanged, verified; RMW out)
__global__ __launch_bounds__(256)
void aggr_kernel(float* __restrict__ out, int n_dst) {
    int d = (blockIdx.x * blockDim.x + threadIdx.x) >> 5;
    int lane = threadIdx.x & 31;
    if (d >= n_dst) return;
    int h = lane >> 3;

    int i   = g_row[d];
    int end = g_row[d + 1];
    float adv = g_adst[d * HEADS + h];

    float4 acc = make_float4(0.f, 0.f, 0.f, 0.f);
    float wsum = 0.f;
    const float4* feat4 = (const float4*)g_feat;

    int   s_cur = (i < end) ? g_csr_s[i] : 0;
    float a_cur = (i < end) ? g_asrc[s_cur * HEADS + h] : 0.f;
    for (; i < end; ) {
        int inext = i + 1;
        int   s_nxt = 0;
        float a_nxt = 0.f;
        if (inext < end) {
            s_nxt = g_csr_s[inext];
            a_nxt = g_asrc[s_nxt * HEADS + h];
        }
        float w = __expf(leaky02(a_cur + adv));
        float4 f = feat4[s_cur * 32 + lane];
        acc.x += w * f.x; acc.y += w * f.y;
        acc.z += w * f.z; acc.w += w * f.w;
        wsum += w;
        s_cur = s_nxt; a_cur = a_nxt;
        i = inext;
    }

    float rs = 1.f / (wsum + 1e-16f);
    float4* out4 = (float4*)out;
    float4 o = out4[d * 32 + lane];
    o.x += acc.x * rs; o.y += acc.y * rs;
    o.z += acc.z * rs; o.w += acc.w * rs;
    out4[d * 32 + lane] = o;
}

// ---------------- FFMA2 GEMM with duplicated-A smem (pack-free a-operands)
// MODE 0: C=feat + alpha_src epilogue. MODE 1: C=out+bias + alpha_dst in loop.
#define BM 128
#define BN 128
#define BK 16
#define TM 8
#define TN 8
#define AD 256   // duplicated-A row width in floats (2*BM)

template <int MODE>
__global__ __launch_bounds__(256, 2)
void gemm128_kernel(const float* __restrict__ A,
                    const float* __restrict__ B,
                    const float* __restrict__ aux,   // att_src (M0) / bias (M1)
                    float* __restrict__ C,
                    float* __restrict__ alpha_out,
                    int nrows) {
    __shared__ __align__(16) float As[2][BK][AD];    // duplicated pairs
    __shared__ __align__(16) float Bs[2][BK][BN];
    __shared__ float xtra[MODE == 0 ? FDIM : FDIM * HEADS];

    int tid = threadIdx.x;
    int tn_idx = tid & 15;
    int tm_idx = tid >> 4;
    int tm0 = tm_idx * TM;
    int tn0 = tn_idx * TN;
    int m0 = blockIdx.x * BM;

    if (MODE == 0) {
        if (tid < FDIM) xtra[tid] = aux[tid];
    } else {
        xtra[tid] = g_fold_v[tid];
        xtra[tid + 256] = g_fold_v[tid + 256];
    }

    u64 acc2[TM][TN / 2];
    #pragma unroll
    for (int i = 0; i < TM; i++)
        #pragma unroll
        for (int j = 0; j < TN / 2; j++) acc2[i][j] = 0ull;

    int af_row[2], af_k4[2];
    int bf_k[2], bf_n4[2];
    #pragma unroll
    for (int i = 0; i < 2; i++) {
        int f = tid + i * 256;
        af_row[i] = f >> 2;
        af_k4[i]  = (f & 3) * 4;
        bf_k[i]   = f >> 5;
        bf_n4[i]  = (f & 31) * 4;
    }

    float4 a_reg[2], b_reg[2];
    const float4 zero4 = make_float4(0.f, 0.f, 0.f, 0.f);

    #pragma unroll
    for (int i = 0; i < 2; i++) {
        int grow = m0 + af_row[i];
        a_reg[i] = (grow < nrows)
            ? *(const float4*)(A + (size_t)grow * FDIM + af_k4[i]) : zero4;
        b_reg[i] = *(const float4*)(B + (size_t)bf_k[i] * FDIM + bf_n4[i]);
    }
    #pragma unroll
    for (int i = 0; i < 2; i++) {
        int r2 = af_row[i] * 2;
        *(float2*)&As[0][af_k4[i] + 0][r2] = make_float2(a_reg[i].x, a_reg[i].x);
        *(float2*)&As[0][af_k4[i] + 1][r2] = make_float2(a_reg[i].y, a_reg[i].y);
        *(float2*)&As[0][af_k4[i] + 2][r2] = make_float2(a_reg[i].z, a_reg[i].z);
        *(float2*)&As[0][af_k4[i] + 3][r2] = make_float2(a_reg[i].w, a_reg[i].w);
        *(float4*)&Bs[0][bf_k[i]][bf_n4[i]] = b_reg[i];
    }
    __syncthreads();

    int h  = tn_idx >> 2;
    int qq = (tn_idx & 3) * 2;
    float av0 = 0.f, av1 = 0.f;

    int buf = 0;
    const int NT = FDIM / BK;
    for (int t = 0; t < NT; t++) {
        if (t + 1 < NT) {
            int kt = (t + 1) * BK;
            #pragma unroll
            for (int i = 0; i < 2; i++) {
                int grow = m0 + af_row[i];
                a_reg[i] = (grow < nrows)
                    ? *(const float4*)(A + (size_t)grow * FDIM + kt + af_k4[i]) : zero4;
                b_reg[i] = *(const float4*)(B + (size_t)(kt + bf_k[i]) * FDIM + bf_n4[i]);
            }
        }

        #pragma unroll
        for (int k = 0; k < BK; k++) {
            // a dup-pairs: 8 pairs = 4 x LDS.128 (broadcast, conflict-free)
            ulonglong2 aq0 = *(const ulonglong2*)&As[buf][k][2 * tm0];
            ulonglong2 aq1 = *(const ulonglong2*)&As[buf][k][2 * tm0 + 4];
            ulonglong2 aq2 = *(const ulonglong2*)&As[buf][k][2 * tm0 + 8];
            ulonglong2 aq3 = *(const ulonglong2*)&As[buf][k][2 * tm0 + 12];
            u64 ad[TM] = {aq0.x, aq0.y, aq1.x, aq1.y,
                          aq2.x, aq2.y, aq3.x, aq3.y};
            ulonglong2 bq0 = *(const ulonglong2*)&Bs[buf][k][tn0];
            ulonglong2 bq1 = *(const ulonglong2*)&Bs[buf][k][tn0 + 4];
            u64 bp[4] = {bq0.x, bq0.y, bq1.x, bq1.y};
            #pragma unroll
            for (int i = 0; i < TM; i++)
                #pragma unroll
                for (int j = 0; j < TN / 2; j++)
                    FMA_F32X2(acc2[i][j], ad[i], bp[j], acc2[i][j]);
            if (MODE == 1) {
                float vv = xtra[(t * BK + k) * HEADS + h];
                av0 += As[buf][k][2 * (tm0 + qq)]     * vv;
                av1 += As[buf][k][2 * (tm0 + qq + 1)] * vv;
            }
        }

        if (t + 1 < NT) {
            int nb = buf ^ 1;
            #pragma unroll
            for (int i = 0; i < 2; i++) {
                int r2 = af_row[i] * 2;
                *(float2*)&As[nb][af_k4[i] + 0][r2] = make_float2(a_reg[i].x, a_reg[i].x);
                *(float2*)&As[nb][af_k4[i] + 1][r2] = make_float2(a_reg[i].y, a_reg[i].y);
                *(float2*)&As[nb][af_k4[i] + 2][r2] = make_float2(a_reg[i].z, a_reg[i].z);
                *(float2*)&As[nb][af_k4[i] + 3][r2] = make_float2(a_reg[i].w, a_reg[i].w);
                *(float4*)&Bs[nb][bf_k[i]][bf_n4[i]] = b_reg[i];
            }
            __syncthreads();
            buf = nb;
        }
    }

    float acc[TM][TN];
    #pragma unroll
    for (int i = 0; i < TM; i++)
        #pragma unroll
        for (int j = 0; j < TN / 2; j++) {
            unsigned lo, hi;
            UNPACK_F32X2(lo, hi, acc2[i][j]);
            acc[i][2 * j]     = __uint_as_float(lo);
            acc[i][2 * j + 1] = __uint_as_float(hi);
        }

    float4 bb0 = zero4, bb1 = zero4;
    if (MODE == 1) {
        bb0 = *(const float4*)(aux + tn0);
        bb1 = *(const float4*)(aux + tn0 + 4);
    }
    #pragma unroll
    for (int i = 0; i < TM; i++) {
        int row = m0 + tm0 + i;
        if (row < nrows) {
            float4 o0 = make_float4(acc[i][0] + bb0.x, acc[i][1] + bb0.y,
                                    acc[i][2] + bb0.z, acc[i][3] + bb0.w);
            float4 o1 = make_float4(acc[i][4] + bb1.x, acc[i][5] + bb1.y,
                                    acc[i][6] + bb1.z, acc[i][7] + bb1.w);
            *(float4*)(C + (size_t)row * FDIM + tn0)     = o0;
            *(float4*)(C + (size_t)row * FDIM + tn0 + 4) = o1;
        }
    }

    if (MODE == 0) {
        float a_att[TN];
        #pragma unroll
        for (int j = 0; j < TN; j++) a_att[j] = xtra[tn0 + j];
        #pragma unroll
        for (int i = 0; i < TM; i++) {
            float p = 0.f;
            #pragma unroll
            for (int j = 0; j < TN; j++) p += acc[i][j] * a_att[j];
            p += __shfl_xor_sync(0xffffffffu, p, 1);
            p += __shfl_xor_sync(0xffffffffu, p, 2);
            if ((tn_idx & 3) == 0) {
                int row = m0 + tm0 + i;
                if (row < nrows) alpha_out[row * HEADS + h] = p;
            }
        }
    } else {
        int r0 = m0 + tm0 + qq;
        if (r0 < nrows)     alpha_out[r0 * HEADS + h]       = av0;
        if (r0 + 1 < nrows) alpha_out[(r0 + 1) * HEADS + h] = av1;
    }
}

// ---------------------------------------------------------------------------
extern "C" void kernel_launch(void* const* d_in, const int* in_sizes, int n_in,
                              void* d_out, int out_size) {
    const float* x_src    = (const float*)d_in[0];
    const float* x_dst    = (const float*)d_in[1];
    const int*   edge_src = (const int*)d_in[2];
    const int*   edge_dst = (const int*)d_in[3];
    int off = (n_in >= 11) ? 5 : 4;
    const float* W_src   = (const float*)d_in[off + 0];
    const float* W_dst   = (const float*)d_in[off + 1];
    const float* att_src = (const float*)d_in[off + 2];
    const float* att_dst = (const float*)d_in[off + 3];
    const float* W_self  = (const float*)d_in[off + 4];
    const float* b_self  = (const float*)d_in[off + 5];
    float* out = (float*)d_out;

    int n_src = in_sizes[0] / FDIM;
    int n_dst = in_sizes[1] / FDIM;
    int E     = in_sizes[2];

    static float* p_feat = nullptr;
    static float* p_asrc = nullptr;
    static float* p_adst = nullptr;
    static cudaStream_t s1 = nullptr, s2 = nullptr;
    static cudaEvent_t ev_fork = nullptr, ev_g1 = nullptr, ev_csr = nullptr;
    if (!p_feat) {
        cudaGetSymbolAddress((void**)&p_feat, g_feat);
        cudaGetSymbolAddress((void**)&p_asrc, g_asrc);
        cudaGetSymbolAddress((void**)&p_adst, g_adst);
        cudaStreamCreateWithFlags(&s1, cudaStreamNonBlocking);
        cudaStreamCreateWithFlags(&s2, cudaStreamNonBlocking);
        cudaEventCreateWithFlags(&ev_fork, cudaEventDisableTiming);
        cudaEventCreateWithFlags(&ev_g1,   cudaEventDisableTiming);
        cudaEventCreateWithFlags(&ev_csr,  cudaEventDisableTiming);
    }

    int nb = (n_dst + SCAN_TILE - 1) / SCAN_TILE;

    // main: fold (needed by gemm<1>)
    fold_kernel<<<1, 128>>>(W_dst, att_dst);

    cudaEventRecord(ev_fork, 0);
    cudaStreamWaitEvent(s1, ev_fork, 0);
    cudaStreamWaitEvent(s2, ev_fork, 0);

    // s2: CSR build
    zero_deg_kernel<<<(n_dst + 255) / 256, 256, 0, s2>>>(n_dst);
    hist_kernel<<<(E + 255) / 256, 256, 0, s2>>>(edge_dst, E);
    scan_local_kernel<<<nb, 256, 0, s2>>>(n_dst);
    scan_bsum_kernel<<<1, 256, 0, s2>>>(nb, n_dst);
    scan_apply_kernel<<<nb, 256, 0, s2>>>(n_dst);
    scatter_kernel<<<(E + 255) / 256, 256, 0, s2>>>(edge_src, edge_dst, E);
    cudaEventRecord(ev_csr, s2);

    // s1: dst GEMM (out self-term + alpha_dst)
    gemm128_kernel<1><<<(n_dst + BM - 1) / BM, 256, 0, s1>>>(
        x_dst, W_self, b_self, out, p_adst, n_dst);
    cudaEventRecord(ev_g1, s1);

    // main: src GEMM (feat + alpha_src)
    gemm128_kernel<0><<<(n_src + BM - 1) / BM, 256>>>(
        x_src, W_src, att_src, p_feat, p_asrc, n_src);

    // join
    cudaStreamWaitEvent(0, ev_g1, 0);
    cudaStreamWaitEvent(0, ev_csr, 0);
    long long total_threads = (long long)n_dst * 32;
    int blocks = (int)((total_threads + 255) / 256);
    aggr_kernel<<<blocks, 256>>>(edge_src ? out : out, n_dst);
}